// round 3
// baseline (speedup 1.0000x reference)
#include <cuda_runtime.h>
#include <cuda_bf16.h>
#include <stdint.h>

#define HID   2048
#define INTER 8192
#define NEXP  8
#define NTOK  16384
#define LN_EPS 1e-5f

// Scratch (device globals: allocation-free per harness rules)
__device__ __nv_bfloat16 g_h[(size_t)NTOK * INTER];   // 256 MB: relu(x@up)^2 in bf16
__device__ float g_scale[NTOK];                       // sum of top-2 routing logits

// ---------------------------------------------------------------------------
// Routing: logits = x @ gate_w [2048x8]; scale = sum of top-2 per token.
// Block = 256 threads = 8 warps; each warp owns 32 tokens (lane -> token).
// x tile transposed through smem so global reads stay coalesced; gate chunk
// cached in smem and read as a broadcast.
// ---------------------------------------------------------------------------
__global__ __launch_bounds__(256) void routing_kernel(
    const float* __restrict__ x, const float* __restrict__ gate_w)
{
    __shared__ float xs[8][32][33];   // [warp][token][k] pitch 33 -> conflict-free
    __shared__ float gws[256];        // 32 k x 8 experts per chunk

    const int w    = threadIdx.x >> 5;
    const int lane = threadIdx.x & 31;
    const int t0   = blockIdx.x * 256;

    float acc[NEXP];
#pragma unroll
    for (int e = 0; e < NEXP; e++) acc[e] = 0.f;

    for (int c = 0; c < HID / 32; ++c) {
        const int k0 = c * 32;
        // load x tile: 32 tokens x 32 k, coalesced (lane = k)
#pragma unroll 8
        for (int r = 0; r < 32; ++r)
            xs[w][r][lane] = x[(size_t)(t0 + w * 32 + r) * HID + k0 + lane];
        gws[threadIdx.x] = gate_w[c * 256 + threadIdx.x];
        __syncthreads();
#pragma unroll
        for (int kk = 0; kk < 32; ++kk) {
            float xv = xs[w][lane][kk];
            const float* g = &gws[kk * NEXP];
#pragma unroll
            for (int e = 0; e < NEXP; e++) acc[e] += xv * g[e];
        }
        __syncthreads();
    }

    float m1 = -1e30f, m2 = -1e30f;
#pragma unroll
    for (int e = 0; e < NEXP; e++) {
        float v = acc[e];
        if (v > m1) { m2 = m1; m1 = v; }
        else if (v > m2) { m2 = v; }
    }
    g_scale[t0 + w * 32 + lane] = m1 + m2;
}

// ---------------------------------------------------------------------------
// SGEMM: C[M,N] = A[M,K] @ B[K,N], 128x128x16 tiles, 256 threads, 8x8 micro.
// MODE 0: up     (A fp32 x,  out -> g_h bf16, epilogue relu^2)
// MODE 1: down   (A bf16 g_h, out fp32 C += acc)
// MODE 2: expert (A fp32 x,  out fp32 C  = acc * g_scale[m])
// ---------------------------------------------------------------------------
#define BM 128
#define BN 128
#define BK 16

template <int MODE>
__global__ __launch_bounds__(256, 2) void gemm_kernel(
    const float* __restrict__ A, const float* __restrict__ B,
    float* __restrict__ C, int M, int N, int K)
{
    __shared__ float As[2][BK][BM + 4];
    __shared__ float Bs[2][BK][BN + 4];

    const int tid = threadIdx.x;
    const int tx  = tid & 15;
    const int ty  = tid >> 4;
    const size_t mBase = (size_t)blockIdx.y * BM;
    const size_t nBase = (size_t)blockIdx.x * BN;

    // loader mappings
    const int arow = tid >> 2;            // fp32 A: 64 rows/pass, 2 passes
    const int acol = (tid & 3) << 2;
    const int hrow = tid >> 1;            // bf16 A: 128 rows, 8 elems/thread
    const int hcol = (tid & 1) << 3;
    const int brow = tid >> 5;            // B: 8 rows/pass, 2 passes
    const int bcol = (tid & 31) << 2;

    float acc[8][8];
#pragma unroll
    for (int i = 0; i < 8; i++)
#pragma unroll
        for (int j = 0; j < 8; j++) acc[i][j] = 0.f;

    float4 ar0, ar1, br0, br1;
    uint4  hr;

    auto ldg_tile = [&](int kt) {
        const size_t k0 = (size_t)kt * BK;
        if (MODE == 1) {
            hr = *(const uint4*)(g_h + (mBase + hrow) * (size_t)K + k0 + hcol);
        } else {
            ar0 = *(const float4*)(A + (mBase + arow)      * (size_t)K + k0 + acol);
            ar1 = *(const float4*)(A + (mBase + arow + 64) * (size_t)K + k0 + acol);
        }
        br0 = *(const float4*)(B + (k0 + brow)     * (size_t)N + nBase + bcol);
        br1 = *(const float4*)(B + (k0 + brow + 8) * (size_t)N + nBase + bcol);
    };
    auto sts_tile = [&](int buf) {
        if (MODE == 1) {
            const __nv_bfloat16* hp = (const __nv_bfloat16*)&hr;
#pragma unroll
            for (int i = 0; i < 8; i++)
                As[buf][hcol + i][hrow] = __bfloat162float(hp[i]);
        } else {
#pragma unroll
            for (int i = 0; i < 4; i++) {
                As[buf][acol + i][arow]      = (&ar0.x)[i];
                As[buf][acol + i][arow + 64] = (&ar1.x)[i];
            }
        }
        *(float4*)&Bs[buf][brow][bcol]     = br0;
        *(float4*)&Bs[buf][brow + 8][bcol] = br1;
    };

    const int KT = K / BK;
    ldg_tile(0);
    sts_tile(0);
    __syncthreads();

    int buf = 0;
    for (int kt = 0; kt < KT; ++kt) {
        if (kt + 1 < KT) ldg_tile(kt + 1);
#pragma unroll
        for (int kk = 0; kk < BK; ++kk) {
            float4 a0 = *(const float4*)&As[buf][kk][ty * 4];
            float4 a1 = *(const float4*)&As[buf][kk][ty * 4 + 64];
            float4 b0 = *(const float4*)&Bs[buf][kk][tx * 4];
            float4 b1 = *(const float4*)&Bs[buf][kk][tx * 4 + 64];
            float a[8] = {a0.x, a0.y, a0.z, a0.w, a1.x, a1.y, a1.z, a1.w};
            float b[8] = {b0.x, b0.y, b0.z, b0.w, b1.x, b1.y, b1.z, b1.w};
#pragma unroll
            for (int i = 0; i < 8; i++)
#pragma unroll
                for (int j = 0; j < 8; j++) acc[i][j] += a[i] * b[j];
        }
        if (kt + 1 < KT) {
            sts_tile(buf ^ 1);
            __syncthreads();
            buf ^= 1;
        }
    }

    // Epilogue
#pragma unroll
    for (int i = 0; i < 8; i++) {
        const int r = (i < 4) ? (ty * 4 + i) : (64 + ty * 4 + i - 4);
        const size_t m = mBase + r;
#pragma unroll
        for (int gc = 0; gc < 2; gc++) {
            const int c0 = tx * 4 + gc * 64;
            const size_t idx = m * (size_t)N + nBase + c0;
            if (MODE == 0) {
                float v[4];
#pragma unroll
                for (int jj = 0; jj < 4; jj++) {
                    float cv = acc[i][gc * 4 + jj];
                    v[jj] = (cv > 0.f) ? cv * cv : 0.f;
                }
                union { __nv_bfloat162 h2[2]; uint2 u; } pk;
                pk.h2[0] = __floats2bfloat162_rn(v[0], v[1]);
                pk.h2[1] = __floats2bfloat162_rn(v[2], v[3]);
                *(uint2*)(g_h + idx) = pk.u;
            } else if (MODE == 1) {
                float4* p = (float4*)(C + idx);
                float4 cv = *p;
                cv.x += acc[i][gc * 4 + 0];
                cv.y += acc[i][gc * 4 + 1];
                cv.z += acc[i][gc * 4 + 2];
                cv.w += acc[i][gc * 4 + 3];
                *p = cv;
            } else {
                const float s = __ldg(&g_scale[m]);
                float4 cv;
                cv.x = acc[i][gc * 4 + 0] * s;
                cv.y = acc[i][gc * 4 + 1] * s;
                cv.z = acc[i][gc * 4 + 2] * s;
                cv.w = acc[i][gc * 4 + 3] * s;
                *(float4*)(C + idx) = cv;
            }
        }
    }
}

// ---------------------------------------------------------------------------
// LayerNorm in place over rows of 2048. One block (256 thr) per token.
// ---------------------------------------------------------------------------
__global__ __launch_bounds__(256) void ln_kernel(
    float* __restrict__ y, const float* __restrict__ gamma,
    const float* __restrict__ beta)
{
    __shared__ float ssum[8], ssum2[8];
    const size_t t = blockIdx.x;
    float* row = y + t * (size_t)HID;
    const int base = threadIdx.x * 8;

    float4 v0 = *(float4*)(row + base);
    float4 v1 = *(float4*)(row + base + 4);
    float vals[8] = {v0.x, v0.y, v0.z, v0.w, v1.x, v1.y, v1.z, v1.w};
    float s = 0.f, s2 = 0.f;
#pragma unroll
    for (int i = 0; i < 8; i++) { s += vals[i]; s2 += vals[i] * vals[i]; }

#pragma unroll
    for (int off = 16; off > 0; off >>= 1) {
        s  += __shfl_xor_sync(0xffffffff, s,  off);
        s2 += __shfl_xor_sync(0xffffffff, s2, off);
    }
    const int warp = threadIdx.x >> 5;
    const int lane = threadIdx.x & 31;
    if (lane == 0) { ssum[warp] = s; ssum2[warp] = s2; }
    __syncthreads();
    s = 0.f; s2 = 0.f;
#pragma unroll
    for (int i = 0; i < 8; i++) { s += ssum[i]; s2 += ssum2[i]; }

    const float mu   = s * (1.f / HID);
    const float var  = s2 * (1.f / HID) - mu * mu;
    const float rstd = rsqrtf(var + LN_EPS);

    float4 g0 = *(const float4*)(gamma + base);
    float4 g1 = *(const float4*)(gamma + base + 4);
    float4 b0 = *(const float4*)(beta + base);
    float4 b1 = *(const float4*)(beta + base + 4);
    float gs[8] = {g0.x, g0.y, g0.z, g0.w, g1.x, g1.y, g1.z, g1.w};
    float bs[8] = {b0.x, b0.y, b0.z, b0.w, b1.x, b1.y, b1.z, b1.w};

    float o[8];
#pragma unroll
    for (int i = 0; i < 8; i++) o[i] = (vals[i] - mu) * rstd * gs[i] + bs[i];
    *(float4*)(row + base)     = make_float4(o[0], o[1], o[2], o[3]);
    *(float4*)(row + base + 4) = make_float4(o[4], o[5], o[6], o[7]);
}

// ---------------------------------------------------------------------------
extern "C" void kernel_launch(void* const* d_in, const int* in_sizes, int n_in,
                              void* d_out, int out_size)
{
    const float* x        = (const float*)d_in[0];  // [4,4096,2048]
    const float* gate_w   = (const float*)d_in[1];  // [2048,8]
    const float* up_w     = (const float*)d_in[2];  // [2048,8192]
    const float* down_w   = (const float*)d_in[3];  // [8192,2048]
    const float* expert_w = (const float*)d_in[4];  // [2048,2048]
    const float* gamma    = (const float*)d_in[5];  // [2048]
    const float* beta     = (const float*)d_in[6];  // [2048]
    float* out = (float*)d_out;                     // [4,4096,2048]

    // 1) routing scales
    routing_kernel<<<NTOK / 256, 256>>>(x, gate_w);
    // 2) moe path: out = scale[m] * (x @ expert_w)
    gemm_kernel<2><<<dim3(HID / BN, NTOK / BM), 256>>>(x, expert_w, out, NTOK, HID, HID);
    // 3) shared path up: g_h = relu(x @ up_w)^2  (bf16)
    gemm_kernel<0><<<dim3(INTER / BN, NTOK / BM), 256>>>(x, up_w, nullptr, NTOK, INTER, HID);
    // 4) shared path down: out += g_h @ down_w
    gemm_kernel<1><<<dim3(HID / BN, NTOK / BM), 256>>>(nullptr, down_w, out, NTOK, HID, INTER);
    // 5) layernorm in place
    ln_kernel<<<NTOK, 256>>>(out, gamma, beta);
}

// round 5
// speedup vs baseline: 4.9556x; 4.9556x over previous
#include <cuda_runtime.h>
#include <cuda_bf16.h>
#include <stdint.h>

#define HID   2048
#define INTER 8192
#define NEXP  8
#define NTOK  16384
#define LN_EPS 1e-5f

// GEMM tiling
#define BM 128
#define BN 128
#define BK 32                         // bf16 elems per K-chunk = 64 B rows
#define NSTAGES 4
#define STG_BYTES (2 * BM * 64)       // A tile 8 KB + B tile 8 KB
#define SMEM_TOTAL (NSTAGES * STG_BYTES)   // 64 KB

// ---------------- scratch (device globals, allocation-free) ----------------
__device__ __align__(16) __nv_bfloat16 g_xh [(size_t)NTOK * HID];
__device__ __align__(16) __nv_bfloat16 g_xl [(size_t)NTOK * HID];
__device__ __align__(16) __nv_bfloat16 g_uwT[(size_t)INTER * HID];   // up_w^T
__device__ __align__(16) __nv_bfloat16 g_dwT[(size_t)HID * INTER];   // down_w^T
__device__ __align__(16) __nv_bfloat16 g_ewTh[(size_t)HID * HID];    // expert_w^T hi
__device__ __align__(16) __nv_bfloat16 g_ewTl[(size_t)HID * HID];    // expert_w^T lo
__device__ __align__(16) __nv_bfloat16 g_h  [(size_t)NTOK * INTER];  // relu(x@up)^2
__device__ float g_scale[NTOK];

// ---------------- PTX helpers (all valid on compute_103) ----------------
__device__ __forceinline__ uint32_t smem_u32(const void* p) {
    uint32_t a;
    asm("{ .reg .u64 t; cvta.to.shared.u64 t, %1; cvt.u32.u64 %0, t; }" : "=r"(a) : "l"(p));
    return a;
}
__device__ __forceinline__ void cp_async16(uint32_t s, const void* g) {
    asm volatile("cp.async.cg.shared.global [%0], [%1], 16;" :: "r"(s), "l"(g) : "memory");
}
__device__ __forceinline__ void cp_commit() { asm volatile("cp.async.commit_group;" ::: "memory"); }
template <int N> __device__ __forceinline__ void cp_wait() {
    asm volatile("cp.async.wait_group %0;" :: "n"(N) : "memory");
}
#define LDSM4(R, addr)                                                         \
    asm volatile("ldmatrix.sync.aligned.m8n8.x4.shared.b16 {%0,%1,%2,%3}, [%4];" \
        : "=r"((R)[0]), "=r"((R)[1]), "=r"((R)[2]), "=r"((R)[3]) : "r"(addr))

__device__ __forceinline__ void mma_bf16(float* d, const uint32_t* a,
                                         uint32_t b0, uint32_t b1) {
    asm volatile(
        "mma.sync.aligned.m16n8k16.row.col.f32.bf16.bf16.f32 "
        "{%0,%1,%2,%3}, {%4,%5,%6,%7}, {%8,%9}, {%0,%1,%2,%3};"
        : "+f"(d[0]), "+f"(d[1]), "+f"(d[2]), "+f"(d[3])
        : "r"(a[0]), "r"(a[1]), "r"(a[2]), "r"(a[3]), "r"(b0), "r"(b1));
}

// ---------------------------------------------------------------------------
// bf16 tensor-core GEMM: D[BM,BN] = A[BM,K] @ B^T (B stored [N,K] K-major).
// MODE 0: up     A=g_xh, B=g_uwT, out -> g_h (bf16, relu^2)
// MODE 1: down   A=g_h,  B=g_dwT, out: C += D
// MODE 2: expert split-bf16 3 terms: (xh,ewTh)+(xh,ewTl)+(xl,ewTh); C = D*scale
// ---------------------------------------------------------------------------
template <int MODE>
__global__ __launch_bounds__(256, 2) void gemm_tc(float* __restrict__ C)
{
    constexpr int K   = (MODE == 1) ? INTER : HID;
    constexpr int KT  = K / BK;
    constexpr int KTT = (MODE == 2) ? 3 * KT : KT;

    extern __shared__ char smem[];
    const uint32_t sb = smem_u32(smem);

    const int tid  = threadIdx.x;
    const int wid  = tid >> 5;
    const int lane = tid & 31;
    const int wm   = wid & 3;          // 4 warps along M
    const int wn   = wid >> 2;         // 2 warps along N
    const int mBase = blockIdx.y * BM;
    const int nBase = blockIdx.x * BN;

    // loader mapping: 2 chunks of 16B for A + 2 for B per thread
    const int lrow = tid >> 2;         // chunk row (per 256-chunk pass)
    const int lseg = tid & 3;

    auto load_chunk = [&](int q) {
        const int term = (MODE == 2) ? (q / KT) : 0;
        const int kk   = (MODE == 2) ? (q - term * KT) : q;
        const __nv_bfloat16 *Ap, *Bp;
        if (MODE == 0)      { Ap = g_xh; Bp = g_uwT; }
        else if (MODE == 1) { Ap = g_h;  Bp = g_dwT; }
        else { Ap = (term == 2) ? g_xl : g_xh; Bp = (term == 1) ? g_ewTl : g_ewTh; }
        const uint32_t base = sb + (q & (NSTAGES - 1)) * STG_BYTES;
        const size_t k0 = (size_t)kk * BK;
#pragma unroll
        for (int i = 0; i < 2; i++) {   // A: rows lrow, lrow+64
            const int row = lrow + i * 64;
            cp_async16(base + row * 64 + ((lseg ^ ((row >> 1) & 3)) << 4),
                       Ap + (size_t)(mBase + row) * K + k0 + lseg * 8);
        }
#pragma unroll
        for (int i = 0; i < 2; i++) {   // B
            const int row = lrow + i * 64;
            cp_async16(base + BM * 64 + row * 64 + ((lseg ^ ((row >> 1) & 3)) << 4),
                       Bp + (size_t)(nBase + row) * K + k0 + lseg * 8);
        }
    };

    float acc[2][8][4];
#pragma unroll
    for (int i = 0; i < 2; i++)
#pragma unroll
        for (int j = 0; j < 8; j++)
#pragma unroll
            for (int v = 0; v < 4; v++) acc[i][j][v] = 0.f;

    // ldmatrix lane address components
    const int g  = lane >> 3;          // which 8x8 matrix
    const int r8 = lane & 7;
    const int rowA0 = wm * 32 + r8 + (g & 1) * 8;   // + mtile*16
    const int rowB0 = wn * 64 + r8 + (g & 1) * 8;   // + ntile*16
    const int segHi = g >> 1;                        // + k16*2

    load_chunk(0); cp_commit();
    load_chunk(1); cp_commit();
    load_chunk(2); cp_commit();

    for (int c = 0; c < KTT; ++c) {
        cp_wait<2>();
        __syncthreads();
        if (c + 3 < KTT) load_chunk(c + 3);
        cp_commit();

        const uint32_t aB = sb + (c & (NSTAGES - 1)) * STG_BYTES;
        const uint32_t bB = aB + BM * 64;
#pragma unroll
        for (int k16 = 0; k16 < 2; k16++) {
            const int seg = k16 * 2 + segHi;
            uint32_t A0[4], A1[4], Bf[4][4];
            {
                const int row = rowA0;
                LDSM4(A0, aB + row * 64 + ((seg ^ ((row >> 1) & 3)) << 4));
            }
            {
                const int row = rowA0 + 16;
                LDSM4(A1, aB + row * 64 + ((seg ^ ((row >> 1) & 3)) << 4));
            }
#pragma unroll
            for (int t = 0; t < 4; t++) {
                const int row = rowB0 + t * 16;
                LDSM4(Bf[t], bB + row * 64 + ((seg ^ ((row >> 1) & 3)) << 4));
            }
#pragma unroll
            for (int nj = 0; nj < 8; nj++) {
                const uint32_t b0 = Bf[nj >> 1][nj & 1];
                const uint32_t b1 = Bf[nj >> 1][2 + (nj & 1)];
                mma_bf16(acc[0][nj], A0, b0, b1);
                mma_bf16(acc[1][nj], A1, b0, b1);
            }
        }
    }

    // ---- epilogue ----
    const int rl = lane >> 2;
    const int cl = (lane & 3) * 2;
#pragma unroll
    for (int mi = 0; mi < 2; mi++) {
        const int r0 = mBase + wm * 32 + mi * 16 + rl;
#pragma unroll
        for (int nj = 0; nj < 8; nj++) {
            const int cc = nBase + wn * 64 + nj * 8 + cl;
            const float* d = acc[mi][nj];
            if (MODE == 0) {
                float a0 = d[0] > 0.f ? d[0] * d[0] : 0.f;
                float a1 = d[1] > 0.f ? d[1] * d[1] : 0.f;
                float a2 = d[2] > 0.f ? d[2] * d[2] : 0.f;
                float a3 = d[3] > 0.f ? d[3] * d[3] : 0.f;
                __nv_bfloat162 p0 = __floats2bfloat162_rn(a0, a1);
                __nv_bfloat162 p1 = __floats2bfloat162_rn(a2, a3);
                *(uint32_t*)(g_h + (size_t)r0 * INTER + cc)       = *(uint32_t*)&p0;
                *(uint32_t*)(g_h + (size_t)(r0 + 8) * INTER + cc) = *(uint32_t*)&p1;
            } else if (MODE == 1) {
                float2* p0 = (float2*)(C + (size_t)r0 * HID + cc);
                float2* p1 = (float2*)(C + (size_t)(r0 + 8) * HID + cc);
                float2 v0 = *p0, v1 = *p1;
                v0.x += d[0]; v0.y += d[1];
                v1.x += d[2]; v1.y += d[3];
                *p0 = v0; *p1 = v1;
            } else {
                const float s0 = g_scale[r0];
                const float s8 = g_scale[r0 + 8];
                *(float2*)(C + (size_t)r0 * HID + cc)       = make_float2(d[0] * s0, d[1] * s0);
                *(float2*)(C + (size_t)(r0 + 8) * HID + cc) = make_float2(d[2] * s8, d[3] * s8);
            }
        }
    }
}

// ---------------------------------------------------------------------------
// x -> hi/lo bf16 split
// ---------------------------------------------------------------------------
__global__ __launch_bounds__(256) void cvt_x_kernel(const float* __restrict__ x)
{
    const size_t i = ((size_t)blockIdx.x * 256 + threadIdx.x) * 4;
    float4 v = *(const float4*)(x + i);
    __nv_bfloat16 h[4], l[4];
#pragma unroll
    for (int j = 0; j < 4; j++) {
        float f = (&v.x)[j];
        h[j] = __float2bfloat16_rn(f);
        l[j] = __float2bfloat16_rn(f - __bfloat162float(h[j]));
    }
    *(uint2*)(g_xh + i) = *(uint2*)h;
    *(uint2*)(g_xl + i) = *(uint2*)l;
}

// ---------------------------------------------------------------------------
// transpose + bf16 convert: dst[c][r] = bf16(src[r][c])
// WHICH 0: g_uwT  1: g_dwT  2: g_ewTh/g_ewTl split
// ---------------------------------------------------------------------------
template <int WHICH>
__global__ __launch_bounds__(256) void trans_cvt_kernel(const float* __restrict__ src, int R, int C)
{
    __shared__ float t[32][33];
    const int bx = blockIdx.x * 32, by = blockIdx.y * 32;
    const int tx = threadIdx.x & 31, ty = threadIdx.x >> 5;
#pragma unroll
    for (int j = 0; j < 32; j += 8)
        t[ty + j][tx] = src[(size_t)(by + ty + j) * C + bx + tx];
    __syncthreads();
#pragma unroll
    for (int j = 0; j < 32; j += 8) {
        const float v = t[tx][ty + j];
        const __nv_bfloat16 h = __float2bfloat16_rn(v);
        const size_t o = (size_t)(bx + ty + j) * R + by + tx;
        if (WHICH == 0) g_uwT[o] = h;
        else if (WHICH == 1) g_dwT[o] = h;
        else {
            g_ewTh[o] = h;
            g_ewTl[o] = __float2bfloat16_rn(v - __bfloat162float(h));
        }
    }
}

// ---------------------------------------------------------------------------
// Routing: scale = sum of top-2 of x @ gate_w (fp32)
// ---------------------------------------------------------------------------
__global__ __launch_bounds__(256) void routing_kernel(
    const float* __restrict__ x, const float* __restrict__ gate_w)
{
    __shared__ float xs[8][32][33];
    __shared__ float gws[256];
    const int w = threadIdx.x >> 5, lane = threadIdx.x & 31;
    const int t0 = blockIdx.x * 256;
    float acc[NEXP];
#pragma unroll
    for (int e = 0; e < NEXP; e++) acc[e] = 0.f;
    for (int c = 0; c < HID / 32; ++c) {
        const int k0 = c * 32;
#pragma unroll 8
        for (int r = 0; r < 32; ++r)
            xs[w][r][lane] = x[(size_t)(t0 + w * 32 + r) * HID + k0 + lane];
        gws[threadIdx.x] = gate_w[c * 256 + threadIdx.x];
        __syncthreads();
#pragma unroll
        for (int kk = 0; kk < 32; ++kk) {
            const float xv = xs[w][lane][kk];
            const float* g = &gws[kk * NEXP];
#pragma unroll
            for (int e = 0; e < NEXP; e++) acc[e] += xv * g[e];
        }
        __syncthreads();
    }
    float m1 = -1e30f, m2 = -1e30f;
#pragma unroll
    for (int e = 0; e < NEXP; e++) {
        const float v = acc[e];
        if (v > m1) { m2 = m1; m1 = v; } else if (v > m2) { m2 = v; }
    }
    g_scale[t0 + w * 32 + lane] = m1 + m2;
}

// ---------------------------------------------------------------------------
// LayerNorm in place
// ---------------------------------------------------------------------------
__global__ __launch_bounds__(256) void ln_kernel(
    float* __restrict__ y, const float* __restrict__ gamma, const float* __restrict__ beta)
{
    __shared__ float ssum[8], ssum2[8];
    float* row = y + (size_t)blockIdx.x * HID;
    const int base = threadIdx.x * 8;
    float4 v0 = *(float4*)(row + base);
    float4 v1 = *(float4*)(row + base + 4);
    float vals[8] = {v0.x, v0.y, v0.z, v0.w, v1.x, v1.y, v1.z, v1.w};
    float s = 0.f, s2 = 0.f;
#pragma unroll
    for (int i = 0; i < 8; i++) { s += vals[i]; s2 += vals[i] * vals[i]; }
#pragma unroll
    for (int off = 16; off > 0; off >>= 1) {
        s  += __shfl_xor_sync(0xffffffff, s,  off);
        s2 += __shfl_xor_sync(0xffffffff, s2, off);
    }
    const int warp = threadIdx.x >> 5, lane = threadIdx.x & 31;
    if (lane == 0) { ssum[warp] = s; ssum2[warp] = s2; }
    __syncthreads();
    s = 0.f; s2 = 0.f;
#pragma unroll
    for (int i = 0; i < 8; i++) { s += ssum[i]; s2 += ssum2[i]; }
    const float mu = s * (1.f / HID);
    const float rstd = rsqrtf(s2 * (1.f / HID) - mu * mu + LN_EPS);
    float4 g0 = *(const float4*)(gamma + base);
    float4 g1 = *(const float4*)(gamma + base + 4);
    float4 b0 = *(const float4*)(beta + base);
    float4 b1 = *(const float4*)(beta + base + 4);
    float gs[8] = {g0.x, g0.y, g0.z, g0.w, g1.x, g1.y, g1.z, g1.w};
    float bs[8] = {b0.x, b0.y, b0.z, b0.w, b1.x, b1.y, b1.z, b1.w};
    float o[8];
#pragma unroll
    for (int i = 0; i < 8; i++) o[i] = (vals[i] - mu) * rstd * gs[i] + bs[i];
    *(float4*)(row + base)     = make_float4(o[0], o[1], o[2], o[3]);
    *(float4*)(row + base + 4) = make_float4(o[4], o[5], o[6], o[7]);
}

// ---------------------------------------------------------------------------
extern "C" void kernel_launch(void* const* d_in, const int* in_sizes, int n_in,
                              void* d_out, int out_size)
{
    const float* x        = (const float*)d_in[0];
    const float* gate_w   = (const float*)d_in[1];
    const float* up_w     = (const float*)d_in[2];
    const float* down_w   = (const float*)d_in[3];
    const float* expert_w = (const float*)d_in[4];
    const float* gamma    = (const float*)d_in[5];
    const float* beta     = (const float*)d_in[6];
    float* out = (float*)d_out;

    static bool attr_done = false;
    if (!attr_done) {
        cudaFuncSetAttribute(gemm_tc<0>, cudaFuncAttributeMaxDynamicSharedMemorySize, SMEM_TOTAL);
        cudaFuncSetAttribute(gemm_tc<1>, cudaFuncAttributeMaxDynamicSharedMemorySize, SMEM_TOTAL);
        cudaFuncSetAttribute(gemm_tc<2>, cudaFuncAttributeMaxDynamicSharedMemorySize, SMEM_TOTAL);
        attr_done = true;
    }

    // operand conversions
    cvt_x_kernel<<<(NTOK * HID) / 1024, 256>>>(x);
    trans_cvt_kernel<0><<<dim3(INTER / 32, HID / 32), 256>>>(up_w,     HID,   INTER);
    trans_cvt_kernel<1><<<dim3(HID / 32, INTER / 32), 256>>>(down_w,   INTER, HID);
    trans_cvt_kernel<2><<<dim3(HID / 32, HID / 32),   256>>>(expert_w, HID,   HID);
    // routing (fp32)
    routing_kernel<<<NTOK / 256, 256>>>(x, gate_w);
    // expert (split-bf16, 3 terms): out = scale * (x @ expert_w)
    gemm_tc<2><<<dim3(HID / BN, NTOK / BM), 256, SMEM_TOTAL>>>(out);
    // up: g_h = relu(x @ up_w)^2
    gemm_tc<0><<<dim3(INTER / BN, NTOK / BM), 256, SMEM_TOTAL>>>(nullptr);
    // down: out += g_h @ down_w
    gemm_tc<1><<<dim3(HID / BN, NTOK / BM), 256, SMEM_TOTAL>>>(out);
    // layernorm
    ln_kernel<<<NTOK, 256>>>(out, gamma, beta);
}